// round 4
// baseline (speedup 1.0000x reference)
#include <cuda_runtime.h>
#include <cstdint>

// ---------------------------------------------------------------------------
// TripletFeatures: M=41, RHO=1, p=20.
// Index set (m outer, n inner): |m*n| <= 20, n >= m, |m|+|n| <= 20.  K = 173.
// Per (b,k):  S = sum_c E[p+m,c]*conj(E[p+m+n,c])
//             out[b,c,k] = Re( S * E[p+n,c] )  (+ sym term when m != n)
// Output contract (verified R3): float32, shape (B, 2, K), REAL PART ONLY.
// ---------------------------------------------------------------------------

struct Tab {
    int n;
    unsigned short pk[224];   // (u) | (v << 8), u = m+20, v = n+20
};

__host__ __device__ constexpr Tab make_tab() {
    Tab t{};
    t.n = 0;
    for (int m = -20; m <= 20; ++m) {
        for (int n = -20; n <= 20; ++n) {
            int am = m < 0 ? -m : m;
            int an = n < 0 ? -n : n;
            if (am * an <= 20 && n >= m && am + an <= 20) {
                t.pk[t.n] = (unsigned short)((m + 20) | ((n + 20) << 8));
                t.n = t.n + 1;
            }
        }
    }
    return t;
}

constexpr int K = make_tab().n;
static_assert(K == 173, "unexpected index-set size");

constexpr int WPB  = 8;      // warps (batches) per block
constexpr int NPOS = 41;     // field positions
constexpr int M_ELEMS = 82;  // floats per input array per batch (41 pos * 2 comp)
constexpr int KITER = (K + 31) / 32;   // 6

__global__ void __launch_bounds__(WPB * 32)
triplet_kernel(const float* __restrict__ er,
               const float* __restrict__ ei,
               float* __restrict__ out,
               int B)
{
    static constexpr Tab TAB = make_tab();

    // Per position: (re0, im0, re1, im1) -> one LDS.128 per operand.
    __shared__ float4 Esh[WPB][NPOS];
    __shared__ unsigned short tab_s[K + 3];

    const int tid  = threadIdx.x;
    const int w    = tid >> 5;
    const int lane = tid & 31;
    const long long b = (long long)blockIdx.x * WPB + w;

    // Stage index table once per block (uniform-stride constant reads).
    for (int j = tid; j < K; j += WPB * 32) tab_s[j] = TAB.pk[j];

    if (b < B) {
        // Stage this batch: coalesced float2 reads from each input.
        const float2* rb = reinterpret_cast<const float2*>(er + b * M_ELEMS);
        const float2* ib = reinterpret_cast<const float2*>(ei + b * M_ELEMS);
        for (int j = lane; j < NPOS; j += 32) {
            const float2 r = rb[j];
            const float2 im = ib[j];
            Esh[w][j] = make_float4(r.x, im.x, r.y, im.y);
        }
    }
    __syncthreads();
    if (b >= B) return;

    float* ob = out + b * (2 * K);
    const float4* Eb = Esh[w];

    #pragma unroll
    for (int i = 0; i < KITER; ++i) {
        const int k = lane + 32 * i;
        if (k < K) {
            const unsigned pk = tab_s[k];
            const int u  = pk & 0xff;        // p + m
            const int v  = pk >> 8;          // p + n
            const int ww = u + v - 20;       // p + m + n

            const float4 U = Eb[u];
            const float4 V = Eb[v];
            const float4 W = Eb[ww];

            // S = sum_c U_c * conj(W_c)
            const float Sr = U.x * W.x + U.y * W.y + U.z * W.z + U.w * W.w;
            const float Si = U.y * W.x - U.x * W.y + U.w * W.z - U.z * W.w;

            // Re(S * V_c)
            float o0 = Sr * V.x - Si * V.y;
            float o1 = Sr * V.z - Si * V.w;

            if (u != v) {
                const float Tr = V.x * W.x + V.y * W.y + V.z * W.z + V.w * W.w;
                const float Ti = V.y * W.x - V.x * W.y + V.w * W.z - V.z * W.w;
                o0 += Tr * U.x - Ti * U.y;
                o1 += Tr * U.z - Ti * U.w;
            }

            ob[k]     = o0;   // out[b, 0, k]
            ob[K + k] = o1;   // out[b, 1, k]
        }
    }
}

extern "C" void kernel_launch(void* const* d_in, const int* in_sizes, int n_in,
                              void* d_out, int out_size)
{
    const float* er = (const float*)d_in[0];   // E_real (B, 41, 2) float32
    const float* ei = (const float*)d_in[1];   // E_imag (B, 41, 2) float32
    float* out = (float*)d_out;                // float32 (B, 2, K) real parts

    const int B = in_sizes[0] / M_ELEMS;
    const int grid = (B + WPB - 1) / WPB;

    triplet_kernel<<<grid, WPB * 32>>>(er, ei, out, B);
}